// round 5
// baseline (speedup 1.0000x reference)
#include <cuda_runtime.h>
#include <cuda_fp16.h>
#include <cstdint>

// Problem dims
#define M_DIM 8192      // 4 * 2048
#define N_DIM 11008
#define K_DIM 4096
// GEMM tiling
#define BM 128
#define BN 128
#define BK 32
#define PAD 8           // row stride 40 halfs = 80B
#define KT (K_DIM / BK) // 128 k-tiles

// Device-global scratch (allocation-free rule: __device__ arrays are sanctioned)
__device__ __half g_x[(size_t)M_DIM * K_DIM];     // ~67 MB, x as fp16
__device__ __half g_deq[(size_t)N_DIM * K_DIM];   // ~90 MB, dequantized weights
__device__ int    g_flags;                        // bit0: x/out fp32, bit1: w int32, bit2: s fp32

// ---------------------------------------------------------------------------
// Dtype detection. fp16->fp32 promoted words have low 13 mantissa bits == 0
// (exact conversion leaves only 10 significant mantissa bits). int8->int32
// widened words have top 24 bits == sign extension. 128-word majority vote.
// ---------------------------------------------------------------------------
__global__ void detect_kernel(const unsigned int* __restrict__ xw,
                              const unsigned int* __restrict__ ww,
                              const unsigned int* __restrict__ sw) {
    __shared__ int cx, cw, cs;
    if (threadIdx.x == 0) { cx = 0; cw = 0; cs = 0; }
    __syncthreads();
    unsigned int vx = xw[threadIdx.x];
    unsigned int vw = ww[threadIdx.x];
    unsigned int vs = sw[threadIdx.x];
    if ((vx & 0x1FFFu) == 0u) atomicAdd(&cx, 1);
    unsigned int t = vw >> 8;
    if (t == 0u || t == 0x00FFFFFFu) atomicAdd(&cw, 1);
    if ((vs & 0x1FFFu) == 0u) atomicAdd(&cs, 1);
    __syncthreads();
    if (threadIdx.x == 0) {
        int f = 0;
        if (cx >= 120) f |= 1;
        if (cw >= 120) f |= 2;
        if (cs >= 120) f |= 4;
        g_flags = f;
    }
}

// ---------------------------------------------------------------------------
// Funnel x into fp16 g_x (exact: values originate as fp16). 8 elems/thread.
// ---------------------------------------------------------------------------
__global__ void convert_x_kernel(const void* __restrict__ xp) {
    const int flags = g_flags;
    size_t t = (size_t)blockIdx.x * blockDim.x + threadIdx.x;  // 4,194,304 threads
    __align__(16) __half out[8];
    if (flags & 1) {
        const float4* p = (const float4*)xp;
        float4 f0 = p[t * 2], f1 = p[t * 2 + 1];
        out[0] = __float2half(f0.x); out[1] = __float2half(f0.y);
        out[2] = __float2half(f0.z); out[3] = __float2half(f0.w);
        out[4] = __float2half(f1.x); out[5] = __float2half(f1.y);
        out[6] = __float2half(f1.z); out[7] = __float2half(f1.w);
    } else {
        *reinterpret_cast<uint4*>(out) = reinterpret_cast<const uint4*>(xp)[t];
    }
    *reinterpret_cast<uint4*>(&g_x[t * 8]) = *reinterpret_cast<const uint4*>(out);
}

// ---------------------------------------------------------------------------
// Dequant: deq[i][j] = nibble * s[i*64 + j/64]
//   byte = w[i*32 + (j/64)/2][j%64]; hi nibble iff (j/64) even
// Each thread produces 8 consecutive j.
// ---------------------------------------------------------------------------
__global__ void dequant_kernel(const void* __restrict__ wp,
                               const void* __restrict__ sp) {
    const int flags = g_flags;
    int t = blockIdx.x * blockDim.x + threadIdx.x;   // 5,636,096 threads exact
    int i      = t >> 9;         // output row 0..11007
    int jp     = t & 511;        // 8-col packet
    int jg     = jp >> 3;        // 64-col group 0..63
    int within = (jp & 7) << 3;  // byte offset within group

    size_t elem = (size_t)(i * 32 + (jg >> 1)) * 64 + within;

    unsigned char bytes[8];
    if (flags & 2) {  // w widened to int32
        const int4* pi = reinterpret_cast<const int4*>((const int*)wp + elem);
        int4 a = pi[0], b = pi[1];
        bytes[0] = (unsigned char)a.x; bytes[1] = (unsigned char)a.y;
        bytes[2] = (unsigned char)a.z; bytes[3] = (unsigned char)a.w;
        bytes[4] = (unsigned char)b.x; bytes[5] = (unsigned char)b.y;
        bytes[6] = (unsigned char)b.z; bytes[7] = (unsigned char)b.w;
    } else {          // raw int8
        *reinterpret_cast<uint2*>(bytes) =
            *reinterpret_cast<const uint2*>((const signed char*)wp + elem);
    }

    float scale = (flags & 4) ? ((const float*)sp)[i * 64 + jg]
                              : __half2float(((const __half*)sp)[i * 64 + jg]);
    bool hi = (jg & 1) == 0;

    __align__(16) __half out[8];
#pragma unroll
    for (int b = 0; b < 8; b++) {
        signed char sc = (signed char)bytes[b];
        int v;
        if (hi) v = sc >> 4;                           // arithmetic shift (MSB nibble)
        else    v = (sc & 15) - ((sc & 8) << 1);       // sign-extended LSB nibble
        out[b] = __float2half(v * scale);              // == fp16 mul RN (exact product in fp32)
    }
    *reinterpret_cast<uint4*>(&g_deq[(size_t)i * K_DIM + ((size_t)jp << 3)]) =
        *reinterpret_cast<const uint4*>(out);
}

// ---------------------------------------------------------------------------
// GEMM: y[m][n] = sum_k x[m][k] * deq[n][k]   (both K-major)
// 128x128x32 CTA tile, 8 warps (2M x 4N), mma.sync.m16n8k16 f16f16f32,
// cp.async double buffer, ldmatrix.
// ---------------------------------------------------------------------------
__device__ __forceinline__ void cp_async16(void* smem, const void* gmem) {
    unsigned sa = (unsigned)__cvta_generic_to_shared(smem);
    asm volatile("cp.async.cg.shared.global [%0], [%1], 16;\n"
                 :: "r"(sa), "l"(gmem) : "memory");
}
__device__ __forceinline__ void cp_commit() {
    asm volatile("cp.async.commit_group;\n" ::: "memory");
}
template <int N>
__device__ __forceinline__ void cp_wait() {
    asm volatile("cp.async.wait_group %0;\n" :: "n"(N) : "memory");
}
__device__ __forceinline__ void ldsm4(uint32_t& r0, uint32_t& r1,
                                      uint32_t& r2, uint32_t& r3, const void* p) {
    unsigned sa = (unsigned)__cvta_generic_to_shared(p);
    asm volatile("ldmatrix.sync.aligned.m8n8.x4.shared.b16 {%0,%1,%2,%3}, [%4];\n"
                 : "=r"(r0), "=r"(r1), "=r"(r2), "=r"(r3) : "r"(sa));
}
__device__ __forceinline__ void mma16816(float* c, const uint32_t* a, const uint32_t* b) {
    asm volatile("mma.sync.aligned.m16n8k16.row.col.f32.f16.f16.f32 "
                 "{%0,%1,%2,%3}, {%4,%5,%6,%7}, {%8,%9}, {%0,%1,%2,%3};\n"
                 : "+f"(c[0]), "+f"(c[1]), "+f"(c[2]), "+f"(c[3])
                 : "r"(a[0]), "r"(a[1]), "r"(a[2]), "r"(a[3]),
                   "r"(b[0]), "r"(b[1]));
}

__global__ __launch_bounds__(256) void gemm_kernel(void* __restrict__ y) {
    __shared__ __align__(16) __half As[2][BM][BK + PAD];
    __shared__ __align__(16) __half Bs[2][BN][BK + PAD];

    const int tid  = threadIdx.x;
    const int lane = tid & 31;
    const int warp = tid >> 5;
    const int wm   = warp & 1;   // warp M (0..1) -> 64 rows
    const int wn   = warp >> 1;  // warp N (0..3) -> 32 cols
    const int bn   = blockIdx.x * BN;
    const int bm   = blockIdx.y * BM;

    const __half* gA = g_x   + (size_t)bm * K_DIM;
    const __half* gB = g_deq + (size_t)bn * K_DIM;

    float acc[4][4][4];
#pragma unroll
    for (int i = 0; i < 4; i++)
#pragma unroll
        for (int j = 0; j < 4; j++)
#pragma unroll
            for (int k = 0; k < 4; k++) acc[i][j][k] = 0.f;

    // prologue: stage 0
#pragma unroll
    for (int p = 0; p < 2; p++) {
        int chunk = tid + p * 256;          // 512 x 16B chunks per operand
        int row = chunk >> 2, c = chunk & 3;
        cp_async16(&As[0][row][c * 8], gA + (size_t)row * K_DIM + c * 8);
        cp_async16(&Bs[0][row][c * 8], gB + (size_t)row * K_DIM + c * 8);
    }
    cp_commit();

    for (int kt = 0; kt < KT; kt++) {
        const int buf = kt & 1;
        if (kt + 1 < KT) {
            const int k0 = (kt + 1) * BK;
            const int nbuf = buf ^ 1;
#pragma unroll
            for (int p = 0; p < 2; p++) {
                int chunk = tid + p * 256;
                int row = chunk >> 2, c = chunk & 3;
                cp_async16(&As[nbuf][row][c * 8], gA + (size_t)row * K_DIM + k0 + c * 8);
                cp_async16(&Bs[nbuf][row][c * 8], gB + (size_t)row * K_DIM + k0 + c * 8);
            }
            cp_commit();
            cp_wait<1>();   // stage kt landed
        } else {
            cp_wait<0>();
        }
        __syncthreads();

#pragma unroll
        for (int ks = 0; ks < 2; ks++) {
            uint32_t a[4][4];
#pragma unroll
            for (int mi = 0; mi < 4; mi++) {
                const __half* p = &As[buf][wm * 64 + mi * 16 + (lane & 15)]
                                         [ks * 16 + ((lane >> 4) << 3)];
                ldsm4(a[mi][0], a[mi][1], a[mi][2], a[mi][3], p);
            }
            uint32_t b[2][4];
#pragma unroll
            for (int ni2 = 0; ni2 < 2; ni2++) {
                const __half* p = &Bs[buf][wn * 32 + ni2 * 16 + (lane & 7) + ((lane >> 4) << 3)]
                                         [ks * 16 + (((lane >> 3) & 1) << 3)];
                // r0=(n0-7,kLo) r1=(n0-7,kHi) r2=(n8-15,kLo) r3=(n8-15,kHi)
                ldsm4(b[ni2][0], b[ni2][1], b[ni2][2], b[ni2][3], p);
            }
#pragma unroll
            for (int mi = 0; mi < 4; mi++)
#pragma unroll
                for (int ni = 0; ni < 4; ni++)
                    mma16816(acc[mi][ni], a[mi], &b[ni >> 1][(ni & 1) * 2]);
        }
        __syncthreads();
    }

    // epilogue: round through fp16 (matches reference quantization), store as
    // fp32 or fp16 depending on detected promotion.
    const int flags = g_flags;
#pragma unroll
    for (int mi = 0; mi < 4; mi++) {
        int m0 = bm + wm * 64 + mi * 16 + (lane >> 2);
#pragma unroll
        for (int ni = 0; ni < 4; ni++) {
            int n = bn + wn * 32 + ni * 8 + (lane & 3) * 2;
            __half h0 = __float2half(acc[mi][ni][0]);
            __half h1 = __float2half(acc[mi][ni][1]);
            __half h2 = __float2half(acc[mi][ni][2]);
            __half h3 = __float2half(acc[mi][ni][3]);
            if (flags & 1) {
                float* yf = (float*)y;
                *reinterpret_cast<float2*>(yf + (size_t)m0 * N_DIM + n) =
                    make_float2(__half2float(h0), __half2float(h1));
                *reinterpret_cast<float2*>(yf + (size_t)(m0 + 8) * N_DIM + n) =
                    make_float2(__half2float(h2), __half2float(h3));
            } else {
                __half* yh = (__half*)y;
                *reinterpret_cast<__half2*>(yh + (size_t)m0 * N_DIM + n) =
                    __halves2half2(h0, h1);
                *reinterpret_cast<__half2*>(yh + (size_t)(m0 + 8) * N_DIM + n) =
                    __halves2half2(h2, h3);
            }
        }
    }
}

// ---------------------------------------------------------------------------
// kernel_launch: identify inputs by element count (order-proof):
//   x = 33,554,432  |  w = 22,544,384  |  s = 704,512
// ---------------------------------------------------------------------------
extern "C" void kernel_launch(void* const* d_in, const int* in_sizes, int n_in,
                              void* d_out, int out_size) {
    const void* x = nullptr;
    const void* w = nullptr;
    const void* s = nullptr;
    for (int i = 0; i < n_in; i++) {
        if      (in_sizes[i] == 33554432) x = d_in[i];
        else if (in_sizes[i] == 22544384) w = d_in[i];
        else if (in_sizes[i] == 704512)   s = d_in[i];
    }

    detect_kernel<<<1, 128>>>((const unsigned int*)x, (const unsigned int*)w,
                              (const unsigned int*)s);
    convert_x_kernel<<<16384, 256>>>(x);     // 33,554,432 / 8 / 256
    dequant_kernel<<<22016, 256>>>(w, s);    // 45,088,768 / 8 / 256

    dim3 grid(N_DIM / BN, M_DIM / BM);       // (86, 64)
    gemm_kernel<<<grid, 256>>>(d_out);
}

// round 8
// speedup vs baseline: 1.1212x; 1.1212x over previous
#include <cuda_runtime.h>
#include <cuda.h>
#include <cuda_fp16.h>
#include <cstdint>

// ---------------------------------------------------------------------------
// Problem dims
// ---------------------------------------------------------------------------
#define M_DIM 8192
#define N_DIM 11008
#define K_DIM 4096

// GEMM tiling (mma.sync consumer, TMA producer)
#define BM 128
#define BN 256
#define BK 64                      // 64 fp16 = 128B row = SW128 atom
#define STAGES 4
#define KTILES (K_DIM / BK)        // 64
#define CLUSTER_M 4                // 4 M-tiles share one B tile via multicast
#define NTILES (N_DIM / BN)        // 43
#define MTILES (M_DIM / BM)        // 64

// SMEM layout
#define SMEM_A_STAGE 16384         // 128 rows x 128B
#define SMEM_B_STAGE 32768         // 256 rows x 128B
#define SMEM_B_SLICE 8192          // 64 rows x 128B
#define SMEM_A_OFF 0
#define SMEM_B_OFF (STAGES * SMEM_A_STAGE)               // 65536
#define BAR_OFF (SMEM_B_OFF + STAGES * SMEM_B_STAGE)     // 196608
#define SMEM_TOTAL (BAR_OFF + 128)
#define STAGE_TX (SMEM_A_STAGE + SMEM_B_STAGE)           // 49152

// Device-global scratch
__device__ __half g_x[(size_t)M_DIM * K_DIM];
__device__ __half g_deq[(size_t)N_DIM * K_DIM];
__device__ int    g_flags;   // bit0: x/out fp32, bit1: w int32, bit2: s fp32

// ---------------------------------------------------------------------------
// PTX helpers (only features R6's ptxas accepted on this target)
// ---------------------------------------------------------------------------
__device__ __forceinline__ uint32_t smem_u32(const void* p) {
    return (uint32_t)__cvta_generic_to_shared(p);
}
__device__ __forceinline__ uint32_t elect_one() {
    uint32_t pred;
    asm volatile("{\n\t.reg .pred p;\n\telect.sync _|p, 0xFFFFFFFF;\n\t"
                 "selp.b32 %0, 1, 0, p;\n\t}" : "=r"(pred));
    return pred;
}
__device__ __forceinline__ uint32_t ctarank() {
    uint32_t r; asm("mov.u32 %0, %%cluster_ctarank;" : "=r"(r)); return r;
}
__device__ __forceinline__ void mbar_init(uint32_t a, uint32_t n) {
    asm volatile("mbarrier.init.shared.b64 [%0], %1;" :: "r"(a), "r"(n) : "memory");
}
__device__ __forceinline__ void mbar_expect_tx(uint32_t a, uint32_t b) {
    asm volatile("mbarrier.arrive.expect_tx.shared.b64 _, [%0], %1;" :: "r"(a), "r"(b) : "memory");
}
__device__ __forceinline__ void mbar_wait(uint32_t a, uint32_t parity) {
    asm volatile("{\n\t.reg .pred P;\n\t"
                 "W_%=:\n\t"
                 "mbarrier.try_wait.parity.acquire.cta.shared::cta.b64 P, [%0], %1, 0x989680;\n\t"
                 "@P bra.uni D_%=;\n\t"
                 "bra.uni W_%=;\n\t"
                 "D_%=:\n\t}" :: "r"(a), "r"(parity) : "memory");
}
__device__ __forceinline__ void mbar_wait_relaxed(uint32_t a, uint32_t parity) {
    asm volatile("{\n\t.reg .pred P;\n\t"
                 "W_%=:\n\t"
                 "mbarrier.try_wait.parity.relaxed.cta.shared::cta.b64 P, [%0], %1, 0x989680;\n\t"
                 "@P bra.uni D_%=;\n\t"
                 "bra.uni W_%=;\n\t"
                 "D_%=:\n\t}" :: "r"(a), "r"(parity) : "memory");
}
__device__ __forceinline__ void mbar_arrive_cluster(uint32_t local_addr, uint32_t rank) {
    asm volatile("{\n\t.reg .b32 ra;\n\t"
                 "mapa.shared::cluster.u32 ra, %0, %1;\n\t"
                 "mbarrier.arrive.shared::cluster.b64 _, [ra];\n\t}"
                 :: "r"(local_addr), "r"(rank) : "memory");
}
__device__ __forceinline__ void tma_load(uint32_t dst, const void* map, int x, int y,
                                         uint32_t mbar) {
    asm volatile("cp.async.bulk.tensor.3d.shared::cta.global.tile.mbarrier::complete_tx::bytes "
                 "[%0], [%1, {%2, %3, %4}], [%5];"
                 :: "r"(dst), "l"(map), "r"(x), "r"(y), "r"(0), "r"(mbar) : "memory");
}
__device__ __forceinline__ void tma_load_mc(uint32_t dst, const void* map, int x, int y,
                                            uint32_t mbar, uint16_t mask) {
    asm volatile("cp.async.bulk.tensor.3d.shared::cluster.global.tile."
                 "mbarrier::complete_tx::bytes.multicast::cluster "
                 "[%0], [%1, {%2, %3, %4}], [%5], %6;"
                 :: "r"(dst), "l"(map), "r"(x), "r"(y), "r"(0), "r"(mbar), "h"(mask) : "memory");
}
__device__ __forceinline__ void cluster_sync() {
    asm volatile("barrier.cluster.arrive.aligned;" ::: "memory");
    asm volatile("barrier.cluster.wait.aligned;" ::: "memory");
}
__device__ __forceinline__ void ldsm4(uint32_t& r0, uint32_t& r1,
                                      uint32_t& r2, uint32_t& r3, uint32_t sa) {
    asm volatile("ldmatrix.sync.aligned.m8n8.x4.shared.b16 {%0,%1,%2,%3}, [%4];\n"
                 : "=r"(r0), "=r"(r1), "=r"(r2), "=r"(r3) : "r"(sa));
}
__device__ __forceinline__ void mma16816(float* c, const uint32_t* a, const uint32_t* b) {
    asm volatile("mma.sync.aligned.m16n8k16.row.col.f32.f16.f16.f32 "
                 "{%0,%1,%2,%3}, {%4,%5,%6,%7}, {%8,%9}, {%0,%1,%2,%3};\n"
                 : "+f"(c[0]), "+f"(c[1]), "+f"(c[2]), "+f"(c[3])
                 : "r"(a[0]), "r"(a[1]), "r"(a[2]), "r"(a[3]),
                   "r"(b[0]), "r"(b[1]));
}
#define SW128(b) ((b) ^ (((b) >> 3) & 0x70))

// ---------------------------------------------------------------------------
// Dtype detection (proven in R5)
// ---------------------------------------------------------------------------
__global__ void detect_kernel(const unsigned int* __restrict__ xw,
                              const unsigned int* __restrict__ ww,
                              const unsigned int* __restrict__ sw) {
    __shared__ int cx, cw, cs;
    if (threadIdx.x == 0) { cx = 0; cw = 0; cs = 0; }
    __syncthreads();
    unsigned int vx = xw[threadIdx.x];
    unsigned int vw = ww[threadIdx.x];
    unsigned int vs = sw[threadIdx.x];
    if ((vx & 0x1FFFu) == 0u) atomicAdd(&cx, 1);
    unsigned int t = vw >> 8;
    if (t == 0u || t == 0x00FFFFFFu) atomicAdd(&cw, 1);
    if ((vs & 0x1FFFu) == 0u) atomicAdd(&cs, 1);
    __syncthreads();
    if (threadIdx.x == 0) {
        int f = 0;
        if (cx >= 120) f |= 1;
        if (cw >= 120) f |= 2;
        if (cs >= 120) f |= 4;
        g_flags = f;
    }
}

// ---------------------------------------------------------------------------
// x -> fp16 funnel (exact)
// ---------------------------------------------------------------------------
__global__ void convert_x_kernel(const void* __restrict__ xp) {
    const int flags = g_flags;
    size_t t = (size_t)blockIdx.x * blockDim.x + threadIdx.x;
    __align__(16) __half out[8];
    if (flags & 1) {
        const float4* p = (const float4*)xp;
        float4 f0 = p[t * 2], f1 = p[t * 2 + 1];
        out[0] = __float2half(f0.x); out[1] = __float2half(f0.y);
        out[2] = __float2half(f0.z); out[3] = __float2half(f0.w);
        out[4] = __float2half(f1.x); out[5] = __float2half(f1.y);
        out[6] = __float2half(f1.z); out[7] = __float2half(f1.w);
    } else {
        *reinterpret_cast<uint4*>(out) = reinterpret_cast<const uint4*>(xp)[t];
    }
    *reinterpret_cast<uint4*>(&g_x[t * 8]) = *reinterpret_cast<const uint4*>(out);
}

// ---------------------------------------------------------------------------
// Q4_0 dequant (proven in R5)
// ---------------------------------------------------------------------------
__global__ void dequant_kernel(const void* __restrict__ wp,
                               const void* __restrict__ sp) {
    const int flags = g_flags;
    int t = blockIdx.x * blockDim.x + threadIdx.x;
    int i      = t >> 9;
    int jp     = t & 511;
    int jg     = jp >> 3;
    int within = (jp & 7) << 3;

    size_t elem = (size_t)(i * 32 + (jg >> 1)) * 64 + within;

    unsigned char bytes[8];
    if (flags & 2) {
        const int4* pi = reinterpret_cast<const int4*>((const int*)wp + elem);
        int4 a = pi[0], b = pi[1];
        bytes[0] = (unsigned char)a.x; bytes[1] = (unsigned char)a.y;
        bytes[2] = (unsigned char)a.z; bytes[3] = (unsigned char)a.w;
        bytes[4] = (unsigned char)b.x; bytes[5] = (unsigned char)b.y;
        bytes[6] = (unsigned char)b.z; bytes[7] = (unsigned char)b.w;
    } else {
        *reinterpret_cast<uint2*>(bytes) =
            *reinterpret_cast<const uint2*>((const signed char*)wp + elem);
    }

    float scale = (flags & 4) ? ((const float*)sp)[i * 64 + jg]
                              : __half2float(((const __half*)sp)[i * 64 + jg]);
    bool hi = (jg & 1) == 0;

    __align__(16) __half out[8];
#pragma unroll
    for (int b = 0; b < 8; b++) {
        signed char sc = (signed char)bytes[b];
        int v;
        if (hi) v = sc >> 4;
        else    v = (sc & 15) - ((sc & 8) << 1);
        out[b] = __float2half(v * scale);
    }
    *reinterpret_cast<uint4*>(&g_deq[(size_t)i * K_DIM + ((size_t)jp << 3)]) =
        *reinterpret_cast<const uint4*>(out);
}

// ---------------------------------------------------------------------------
// GEMM: grid (43, 64), cluster (1,4,1). 288 threads:
//   warps 0-7: mma.sync consumers (2M x 4N, warp tile 64x64)
//   warp 8:    TMA producer (A per-CTA, B slice multicast across 4 M-tiles)
// 4-stage pipeline, SW128 tiles, full/empty mbarriers (empty released
// cluster-wide so no peer multicasts into a buffer still being read).
// ---------------------------------------------------------------------------
__global__ void __launch_bounds__(288, 1) gemm_tc(
    const __grid_constant__ CUtensorMap tmapA,
    const __grid_constant__ CUtensorMap tmapB,
    void* __restrict__ y)
{
    extern __shared__ char smem[];
    const uint32_t sb   = smem_u32(smem);
    const int tid  = threadIdx.x;
    const int lane = tid & 31;
    const int warp = tid >> 5;
    const uint32_t rank = ctarank();
    const int ntile = blockIdx.x;
    const int mtile = blockIdx.y;

    const uint32_t full0  = sb + BAR_OFF;        // full[s]  = full0 + 8s
    const uint32_t empty0 = sb + BAR_OFF + 32;   // empty[s] = empty0 + 8s

    if (tid == 0) {
#pragma unroll
        for (int s = 0; s < STAGES; s++) {
            mbar_init(full0 + s * 8, 1);            // tx-based
            mbar_init(empty0 + s * 8, CLUSTER_M);   // 4 consumer releases
        }
    }
    __syncthreads();
    cluster_sync();   // all cluster barriers live before any multicast

    if (warp == 8) {
        // ---------------- TMA producer ----------------
        if (elect_one()) {
            int stage = 0, phase = 1;   // first STAGES empty-waits pass
            for (int kt = 0; kt < KTILES; kt++) {
                mbar_wait_relaxed(empty0 + stage * 8, phase);
                uint32_t fb = full0 + stage * 8;
                mbar_expect_tx(fb, STAGE_TX);
                tma_load(sb + SMEM_A_OFF + stage * SMEM_A_STAGE, &tmapA,
                         kt * BK, mtile * BM, fb);
                tma_load_mc(sb + SMEM_B_OFF + stage * SMEM_B_STAGE + rank * SMEM_B_SLICE,
                            &tmapB, kt * BK, ntile * BN + (int)rank * 64, fb, 0xF);
                if (++stage == STAGES) { stage = 0; phase ^= 1; }
            }
        }
    } else {
        // ---------------- consumers (warps 0-7) ----------------
        const int wm = warp & 1;    // 0..1 -> 64 rows
        const int wn = warp >> 1;   // 0..3 -> 64 cols

        float acc[4][8][4];
#pragma unroll
        for (int i = 0; i < 4; i++)
#pragma unroll
            for (int j = 0; j < 8; j++)
#pragma unroll
                for (int k = 0; k < 4; k++) acc[i][j][k] = 0.f;

        // per-thread ldmatrix byte-offset bases (within a stage tile)
        const int a_off0 = (wm * 64 + (lane & 15)) * 128 + (((lane >> 4) << 3) << 1);
        const int b_off0 = (wn * 64 + (lane & 7) + ((lane >> 4) << 3)) * 128
                         + ((((lane >> 3) & 1) << 3) << 1);

        int stage = 0, phase = 0;
        for (int kt = 0; kt < KTILES; kt++) {
            mbar_wait(full0 + stage * 8, phase);
            const uint32_t a_base = sb + SMEM_A_OFF + stage * SMEM_A_STAGE;
            const uint32_t b_base = sb + SMEM_B_OFF + stage * SMEM_B_STAGE;

#pragma unroll
            for (int ks = 0; ks < 4; ks++) {
                uint32_t a[4][4];
#pragma unroll
                for (int mi = 0; mi < 4; mi++) {
                    int byte = a_off0 + mi * 2048 + ks * 32;
                    ldsm4(a[mi][0], a[mi][1], a[mi][2], a[mi][3], a_base + SW128(byte));
                }
                uint32_t b[4][4];
#pragma unroll
                for (int ni2 = 0; ni2 < 4; ni2++) {
                    int byte = b_off0 + ni2 * 2048 + ks * 32;
                    ldsm4(b[ni2][0], b[ni2][1], b[ni2][2], b[ni2][3], b_base + SW128(byte));
                }
#pragma unroll
                for (int mi = 0; mi < 4; mi++)
#pragma unroll
                    for (int ni = 0; ni < 8; ni++)
                        mma16816(acc[mi][ni], a[mi], &b[ni >> 1][(ni & 1) * 2]);
            }

            asm volatile("bar.sync 1, 256;" ::: "memory");  // 8 consumer warps done
            if (tid == 0) {
#pragma unroll
                for (int r = 0; r < CLUSTER_M; r++)
                    mbar_arrive_cluster(empty0 + stage * 8, r);
            }
            if (++stage == STAGES) { stage = 0; phase ^= 1; }
        }

        // ---------------- epilogue: round through fp16, store ----------------
        const int flags = g_flags;
        const size_t base_m = (size_t)mtile * BM + wm * 64;
        const int base_n = ntile * BN + wn * 64;
#pragma unroll
        for (int mi = 0; mi < 4; mi++) {
            size_t m0 = base_m + mi * 16 + (lane >> 2);
#pragma unroll
            for (int ni = 0; ni < 8; ni++) {
                int n = base_n + ni * 8 + (lane & 3) * 2;
                __half h0 = __float2half(acc[mi][ni][0]);
                __half h1 = __float2half(acc[mi][ni][1]);
                __half h2 = __float2half(acc[mi][ni][2]);
                __half h3 = __float2half(acc[mi][ni][3]);
                if (flags & 1) {
                    float* yf = (float*)y;
                    *reinterpret_cast<float2*>(yf + m0 * N_DIM + n) =
                        make_float2(__half2float(h0), __half2float(h1));
                    *reinterpret_cast<float2*>(yf + (m0 + 8) * N_DIM + n) =
                        make_float2(__half2float(h2), __half2float(h3));
                } else {
                    __half* yh = (__half*)y;
                    *reinterpret_cast<__half2*>(yh + m0 * N_DIM + n) =
                        __halves2half2(h0, h1);
                    *reinterpret_cast<__half2*>(yh + (m0 + 8) * N_DIM + n) =
                        __halves2half2(h2, h3);
                }
            }
        }
    }

    cluster_sync();   // no CTA exits while peer multicasts may target its SMEM
}

// ---------------------------------------------------------------------------
// kernel_launch — inputs by element count: x=33,554,432 w=22,544,384 s=704,512
// ---------------------------------------------------------------------------
typedef CUresult (*EncodeFn)(CUtensorMap*, CUtensorMapDataType, cuuint32_t, void*,
                             const cuuint64_t*, const cuuint64_t*, const cuuint32_t*,
                             const cuuint32_t*, CUtensorMapInterleave, CUtensorMapSwizzle,
                             CUtensorMapL2promotion, CUtensorMapFloatOOBfill);

extern "C" void kernel_launch(void* const* d_in, const int* in_sizes, int n_in,
                              void* d_out, int out_size) {
    const void* x = nullptr; const void* w = nullptr; const void* s = nullptr;
    for (int i = 0; i < n_in; i++) {
        if      (in_sizes[i] == 33554432) x = d_in[i];
        else if (in_sizes[i] == 22544384) w = d_in[i];
        else if (in_sizes[i] == 704512)   s = d_in[i];
    }

    detect_kernel<<<1, 128>>>((const unsigned int*)x, (const unsigned int*)w,
                              (const unsigned int*)s);
    convert_x_kernel<<<16384, 256>>>(x);
    dequant_kernel<<<22016, 256>>>(w, s);

    static CUtensorMap tA, tB;
    static bool built = false;
    if (!built) {
        void* encode_raw = nullptr;
        cudaDriverEntryPointQueryResult qr;
        cudaGetDriverEntryPointByVersion("cuTensorMapEncodeTiled", &encode_raw, 12000,
                                         cudaEnableDefault, &qr);
        EncodeFn encode = (EncodeFn)encode_raw;
        void* pa = nullptr; void* pb = nullptr;
        cudaGetSymbolAddress(&pa, g_x);
        cudaGetSymbolAddress(&pb, g_deq);

        cuuint64_t dA[3] = {K_DIM, M_DIM, 1};
        cuuint64_t sA[2] = {K_DIM * 2ull, (cuuint64_t)K_DIM * M_DIM * 2ull};
        cuuint32_t bA[3] = {BK, BM, 1};
        cuuint32_t eS[3] = {1, 1, 1};
        encode(&tA, CU_TENSOR_MAP_DATA_TYPE_FLOAT16, 3, pa, dA, sA, bA, eS,
               CU_TENSOR_MAP_INTERLEAVE_NONE, CU_TENSOR_MAP_SWIZZLE_128B,
               CU_TENSOR_MAP_L2_PROMOTION_L2_128B, CU_TENSOR_MAP_FLOAT_OOB_FILL_NONE);

        cuuint64_t dB[3] = {K_DIM, N_DIM, 1};
        cuuint64_t sB[2] = {K_DIM * 2ull, (cuuint64_t)K_DIM * N_DIM * 2ull};
        cuuint32_t bB[3] = {BK, 64, 1};   // one cooperative slice (64 N-rows)
        encode(&tB, CU_TENSOR_MAP_DATA_TYPE_FLOAT16, 3, pb, dB, sB, bB, eS,
               CU_TENSOR_MAP_INTERLEAVE_NONE, CU_TENSOR_MAP_SWIZZLE_128B,
               CU_TENSOR_MAP_L2_PROMOTION_L2_128B, CU_TENSOR_MAP_FLOAT_OOB_FILL_NONE);

        cudaFuncSetAttribute(gemm_tc, cudaFuncAttributeMaxDynamicSharedMemorySize,
                             SMEM_TOTAL);
        built = true;
    }

    cudaLaunchConfig_t cfg = {};
    cfg.gridDim  = {NTILES, MTILES, 1};   // (43, 64)
    cfg.blockDim = {288, 1, 1};
    cfg.dynamicSmemBytes = SMEM_TOTAL;
    cfg.stream = 0;
    cudaLaunchAttribute attrs[1];
    attrs[0].id = cudaLaunchAttributeClusterDimension;
    attrs[0].val.clusterDim = {1, CLUSTER_M, 1};
    cfg.attrs = attrs;
    cfg.numAttrs = 1;
    cudaLaunchKernelEx(&cfg, gemm_tc, tA, tB, d_out);
}

// round 9
// speedup vs baseline: 1.1632x; 1.0375x over previous
#include <cuda_runtime.h>
#include <cuda.h>
#include <cuda_fp16.h>
#include <cstdint>

// ---------------------------------------------------------------------------
// Problem dims
// ---------------------------------------------------------------------------
#define M_DIM 8192
#define N_DIM 11008
#define K_DIM 4096

#define BM 128
#define BN 256
#define BK 64                      // 64 fp16 = 128B row = SW128 atom
#define STAGES 4
#define KTILES (K_DIM / BK)        // 64
#define CLUSTER_M 4
#define NTILES (N_DIM / BN)        // 43
#define MTILES (M_DIM / BM)        // 64

#define NWARPS_C 16                // consumer warps (4 per SMSP)
#define NTHREADS (NWARPS_C * 32 + 32)   // 544: +1 producer warp

// SMEM layout
#define SMEM_A_STAGE 16384
#define SMEM_B_STAGE 32768
#define SMEM_B_SLICE 8192
#define SMEM_A_OFF 0
#define SMEM_B_OFF (STAGES * SMEM_A_STAGE)               // 65536
#define BAR_OFF (SMEM_B_OFF + STAGES * SMEM_B_STAGE)     // 196608
#define SMEM_TOTAL (BAR_OFF + 128)
#define STAGE_TX (SMEM_A_STAGE + SMEM_B_STAGE)           // 49152

// Device-global scratch
__device__ __half g_x[(size_t)M_DIM * K_DIM];
__device__ __half g_deq[(size_t)N_DIM * K_DIM];
__device__ int    g_flags;   // bit0: x/out fp32, bit1: w int32, bit2: s fp32

// ---------------------------------------------------------------------------
// PTX helpers
// ---------------------------------------------------------------------------
__device__ __forceinline__ uint32_t smem_u32(const void* p) {
    return (uint32_t)__cvta_generic_to_shared(p);
}
__device__ __forceinline__ uint32_t elect_one() {
    uint32_t pred;
    asm volatile("{\n\t.reg .pred p;\n\telect.sync _|p, 0xFFFFFFFF;\n\t"
                 "selp.b32 %0, 1, 0, p;\n\t}" : "=r"(pred));
    return pred;
}
__device__ __forceinline__ uint32_t ctarank() {
    uint32_t r; asm("mov.u32 %0, %%cluster_ctarank;" : "=r"(r)); return r;
}
__device__ __forceinline__ void mbar_init(uint32_t a, uint32_t n) {
    asm volatile("mbarrier.init.shared.b64 [%0], %1;" :: "r"(a), "r"(n) : "memory");
}
__device__ __forceinline__ void mbar_expect_tx(uint32_t a, uint32_t b) {
    asm volatile("mbarrier.arrive.expect_tx.shared.b64 _, [%0], %1;" :: "r"(a), "r"(b) : "memory");
}
__device__ __forceinline__ void mbar_wait(uint32_t a, uint32_t parity) {
    asm volatile("{\n\t.reg .pred P;\n\t"
                 "W_%=:\n\t"
                 "mbarrier.try_wait.parity.acquire.cta.shared::cta.b64 P, [%0], %1, 0x989680;\n\t"
                 "@P bra.uni D_%=;\n\t"
                 "bra.uni W_%=;\n\t"
                 "D_%=:\n\t}" :: "r"(a), "r"(parity) : "memory");
}
__device__ __forceinline__ void mbar_wait_relaxed(uint32_t a, uint32_t parity) {
    asm volatile("{\n\t.reg .pred P;\n\t"
                 "W_%=:\n\t"
                 "mbarrier.try_wait.parity.relaxed.cta.shared::cta.b64 P, [%0], %1, 0x989680;\n\t"
                 "@P bra.uni D_%=;\n\t"
                 "bra.uni W_%=;\n\t"
                 "D_%=:\n\t}" :: "r"(a), "r"(parity) : "memory");
}
__device__ __forceinline__ void mbar_arrive_cluster(uint32_t local_addr, uint32_t rank) {
    asm volatile("{\n\t.reg .b32 ra;\n\t"
                 "mapa.shared::cluster.u32 ra, %0, %1;\n\t"
                 "mbarrier.arrive.shared::cluster.b64 _, [ra];\n\t}"
                 :: "r"(local_addr), "r"(rank) : "memory");
}
__device__ __forceinline__ void tma_load(uint32_t dst, const void* map, int x, int y,
                                         uint32_t mbar) {
    asm volatile("cp.async.bulk.tensor.3d.shared::cta.global.tile.mbarrier::complete_tx::bytes "
                 "[%0], [%1, {%2, %3, %4}], [%5];"
                 :: "r"(dst), "l"(map), "r"(x), "r"(y), "r"(0), "r"(mbar) : "memory");
}
__device__ __forceinline__ void tma_load_mc(uint32_t dst, const void* map, int x, int y,
                                            uint32_t mbar, uint16_t mask) {
    asm volatile("cp.async.bulk.tensor.3d.shared::cluster.global.tile."
                 "mbarrier::complete_tx::bytes.multicast::cluster "
                 "[%0], [%1, {%2, %3, %4}], [%5], %6;"
                 :: "r"(dst), "l"(map), "r"(x), "r"(y), "r"(0), "r"(mbar), "h"(mask) : "memory");
}
__device__ __forceinline__ void cluster_sync() {
    asm volatile("barrier.cluster.arrive.aligned;" ::: "memory");
    asm volatile("barrier.cluster.wait.aligned;" ::: "memory");
}
__device__ __forceinline__ void ldsm4(uint32_t& r0, uint32_t& r1,
                                      uint32_t& r2, uint32_t& r3, uint32_t sa) {
    asm volatile("ldmatrix.sync.aligned.m8n8.x4.shared.b16 {%0,%1,%2,%3}, [%4];\n"
                 : "=r"(r0), "=r"(r1), "=r"(r2), "=r"(r3) : "r"(sa));
}
__device__ __forceinline__ void mma16816(float* c, const uint32_t* a, const uint32_t* b) {
    asm volatile("mma.sync.aligned.m16n8k16.row.col.f32.f16.f16.f32 "
                 "{%0,%1,%2,%3}, {%4,%5,%6,%7}, {%8,%9}, {%0,%1,%2,%3};\n"
                 : "+f"(c[0]), "+f"(c[1]), "+f"(c[2]), "+f"(c[3])
                 : "r"(a[0]), "r"(a[1]), "r"(a[2]), "r"(a[3]),
                   "r"(b[0]), "r"(b[1]));
}
#define SW128(b) ((b) ^ (((b) >> 3) & 0x70))

// ---------------------------------------------------------------------------
// Dtype detection (proven)
// ---------------------------------------------------------------------------
__global__ void detect_kernel(const unsigned int* __restrict__ xw,
                              const unsigned int* __restrict__ ww,
                              const unsigned int* __restrict__ sw) {
    __shared__ int cx, cw, cs;
    if (threadIdx.x == 0) { cx = 0; cw = 0; cs = 0; }
    __syncthreads();
    unsigned int vx = xw[threadIdx.x];
    unsigned int vw = ww[threadIdx.x];
    unsigned int vs = sw[threadIdx.x];
    if ((vx & 0x1FFFu) == 0u) atomicAdd(&cx, 1);
    unsigned int t = vw >> 8;
    if (t == 0u || t == 0x00FFFFFFu) atomicAdd(&cw, 1);
    if ((vs & 0x1FFFu) == 0u) atomicAdd(&cs, 1);
    __syncthreads();
    if (threadIdx.x == 0) {
        int f = 0;
        if (cx >= 120) f |= 1;
        if (cw >= 120) f |= 2;
        if (cs >= 120) f |= 4;
        g_flags = f;
    }
}

// ---------------------------------------------------------------------------
// x -> fp16 funnel (exact)
// ---------------------------------------------------------------------------
__global__ void convert_x_kernel(const void* __restrict__ xp) {
    const int flags = g_flags;
    size_t t = (size_t)blockIdx.x * blockDim.x + threadIdx.x;
    __align__(16) __half out[8];
    if (flags & 1) {
        const float4* p = (const float4*)xp;
        float4 f0 = p[t * 2], f1 = p[t * 2 + 1];
        out[0] = __float2half(f0.x); out[1] = __float2half(f0.y);
        out[2] = __float2half(f0.z); out[3] = __float2half(f0.w);
        out[4] = __float2half(f1.x); out[5] = __float2half(f1.y);
        out[6] = __float2half(f1.z); out[7] = __float2half(f1.w);
    } else {
        *reinterpret_cast<uint4*>(out) = reinterpret_cast<const uint4*>(xp)[t];
    }
    *reinterpret_cast<uint4*>(&g_x[t * 8]) = *reinterpret_cast<const uint4*>(out);
}

// ---------------------------------------------------------------------------
// Q4_0 dequant (proven)
// ---------------------------------------------------------------------------
__global__ void dequant_kernel(const void* __restrict__ wp,
                               const void* __restrict__ sp) {
    const int flags = g_flags;
    int t = blockIdx.x * blockDim.x + threadIdx.x;
    int i      = t >> 9;
    int jp     = t & 511;
    int jg     = jp >> 3;
    int within = (jp & 7) << 3;

    size_t elem = (size_t)(i * 32 + (jg >> 1)) * 64 + within;

    unsigned char bytes[8];
    if (flags & 2) {
        const int4* pi = reinterpret_cast<const int4*>((const int*)wp + elem);
        int4 a = pi[0], b = pi[1];
        bytes[0] = (unsigned char)a.x; bytes[1] = (unsigned char)a.y;
        bytes[2] = (unsigned char)a.z; bytes[3] = (unsigned char)a.w;
        bytes[4] = (unsigned char)b.x; bytes[5] = (unsigned char)b.y;
        bytes[6] = (unsigned char)b.z; bytes[7] = (unsigned char)b.w;
    } else {
        *reinterpret_cast<uint2*>(bytes) =
            *reinterpret_cast<const uint2*>((const signed char*)wp + elem);
    }

    float scale = (flags & 4) ? ((const float*)sp)[i * 64 + jg]
                              : __half2float(((const __half*)sp)[i * 64 + jg]);
    bool hi = (jg & 1) == 0;

    __align__(16) __half out[8];
#pragma unroll
    for (int b = 0; b < 8; b++) {
        signed char sc = (signed char)bytes[b];
        int v;
        if (hi) v = sc >> 4;
        else    v = (sc & 15) - ((sc & 8) << 1);
        out[b] = __float2half(v * scale);
    }
    *reinterpret_cast<uint4*>(&g_deq[(size_t)i * K_DIM + ((size_t)jp << 3)]) =
        *reinterpret_cast<const uint4*>(out);
}

// ---------------------------------------------------------------------------
// GEMM: grid (43, 64), cluster (1,4,1). 544 threads:
//   warps 0-15: mma.sync consumers (4M x 4N, warp tile 32x64) — 4 per SMSP
//   warp 16:    TMA producer (A per-CTA, B slice multicast)
// Per-warp cluster-wide release (empty count = 64) — no bar.sync per stage.
// ---------------------------------------------------------------------------
__global__ void __launch_bounds__(NTHREADS, 1) gemm_tc(
    const __grid_constant__ CUtensorMap tmapA,
    const __grid_constant__ CUtensorMap tmapB,
    void* __restrict__ y)
{
    extern __shared__ char smem[];
    const uint32_t sb   = smem_u32(smem);
    const int tid  = threadIdx.x;
    const int lane = tid & 31;
    const int warp = tid >> 5;
    const uint32_t rank = ctarank();
    const int ntile = blockIdx.x;
    const int mtile = blockIdx.y;

    const uint32_t full0  = sb + BAR_OFF;        // full[s]  = full0 + 8s
    const uint32_t empty0 = sb + BAR_OFF + 32;   // empty[s] = empty0 + 8s

    if (tid == 0) {
#pragma unroll
        for (int s = 0; s < STAGES; s++) {
            mbar_init(full0 + s * 8, 1);                      // tx-based
            mbar_init(empty0 + s * 8, NWARPS_C * CLUSTER_M);  // 64 warp releases
        }
    }
    __syncthreads();
    cluster_sync();

    if (warp == NWARPS_C) {
        // ---------------- TMA producer ----------------
        if (elect_one()) {
            int stage = 0, phase = 1;
            for (int kt = 0; kt < KTILES; kt++) {
                mbar_wait_relaxed(empty0 + stage * 8, phase);
                uint32_t fb = full0 + stage * 8;
                mbar_expect_tx(fb, STAGE_TX);
                tma_load(sb + SMEM_A_OFF + stage * SMEM_A_STAGE, &tmapA,
                         kt * BK, mtile * BM, fb);
                tma_load_mc(sb + SMEM_B_OFF + stage * SMEM_B_STAGE + rank * SMEM_B_SLICE,
                            &tmapB, kt * BK, ntile * BN + (int)rank * 64, fb, 0xF);
                if (++stage == STAGES) { stage = 0; phase ^= 1; }
            }
        }
    } else {
        // ---------------- consumers (warps 0-15) ----------------
        const int wm = warp & 3;    // 0..3 -> 32 rows each
        const int wn = warp >> 2;   // 0..3 -> 64 cols each

        float acc[2][8][4];
#pragma unroll
        for (int i = 0; i < 2; i++)
#pragma unroll
            for (int j = 0; j < 8; j++)
#pragma unroll
                for (int k = 0; k < 4; k++) acc[i][j][k] = 0.f;

        const int a_off0 = (wm * 32 + (lane & 15)) * 128 + (((lane >> 4) << 3) << 1);
        const int b_off0 = (wn * 64 + (lane & 7) + ((lane >> 4) << 3)) * 128
                         + ((((lane >> 3) & 1) << 3) << 1);

        int stage = 0, phase = 0;
        for (int kt = 0; kt < KTILES; kt++) {
            mbar_wait(full0 + stage * 8, phase);
            const uint32_t a_base = sb + SMEM_A_OFF + stage * SMEM_A_STAGE;
            const uint32_t b_base = sb + SMEM_B_OFF + stage * SMEM_B_STAGE;

#pragma unroll
            for (int ks = 0; ks < 4; ks++) {
                uint32_t a[2][4];
#pragma unroll
                for (int mi = 0; mi < 2; mi++) {
                    int byte = a_off0 + mi * 2048 + ks * 32;
                    ldsm4(a[mi][0], a[mi][1], a[mi][2], a[mi][3], a_base + SW128(byte));
                }
                uint32_t b[4][4];
#pragma unroll
                for (int ni2 = 0; ni2 < 4; ni2++) {
                    int byte = b_off0 + ni2 * 2048 + ks * 32;
                    ldsm4(b[ni2][0], b[ni2][1], b[ni2][2], b[ni2][3], b_base + SW128(byte));
                }
#pragma unroll
                for (int mi = 0; mi < 2; mi++)
#pragma unroll
                    for (int ni = 0; ni < 8; ni++)
                        mma16816(acc[mi][ni], a[mi], &b[ni >> 1][(ni & 1) * 2]);
            }

            // per-warp cluster-wide release (64 arrivals total per stage)
            if (elect_one()) {
#pragma unroll
                for (int r = 0; r < CLUSTER_M; r++)
                    mbar_arrive_cluster(empty0 + stage * 8, r);
            }
            if (++stage == STAGES) { stage = 0; phase ^= 1; }
        }

        // ---------------- epilogue ----------------
        const int flags = g_flags;
        const size_t base_m = (size_t)mtile * BM + wm * 32;
        const int base_n = ntile * BN + wn * 64;
#pragma unroll
        for (int mi = 0; mi < 2; mi++) {
            size_t m0 = base_m + mi * 16 + (lane >> 2);
#pragma unroll
            for (int ni = 0; ni < 8; ni++) {
                int n = base_n + ni * 8 + (lane & 3) * 2;
                __half h0 = __float2half(acc[mi][ni][0]);
                __half h1 = __float2half(acc[mi][ni][1]);
                __half h2 = __float2half(acc[mi][ni][2]);
                __half h3 = __float2half(acc[mi][ni][3]);
                if (flags & 1) {
                    float* yf = (float*)y;
                    *reinterpret_cast<float2*>(yf + m0 * N_DIM + n) =
                        make_float2(__half2float(h0), __half2float(h1));
                    *reinterpret_cast<float2*>(yf + (m0 + 8) * N_DIM + n) =
                        make_float2(__half2float(h2), __half2float(h3));
                } else {
                    __half* yh = (__half*)y;
                    *reinterpret_cast<__half2*>(yh + m0 * N_DIM + n) =
                        __halves2half2(h0, h1);
                    *reinterpret_cast<__half2*>(yh + (m0 + 8) * N_DIM + n) =
                        __halves2half2(h2, h3);
                }
            }
        }
    }

    cluster_sync();
}

// ---------------------------------------------------------------------------
// kernel_launch — inputs by element count: x=33,554,432 w=22,544,384 s=704,512
// ---------------------------------------------------------------------------
typedef CUresult (*EncodeFn)(CUtensorMap*, CUtensorMapDataType, cuuint32_t, void*,
                             const cuuint64_t*, const cuuint64_t*, const cuuint32_t*,
                             const cuuint32_t*, CUtensorMapInterleave, CUtensorMapSwizzle,
                             CUtensorMapL2promotion, CUtensorMapFloatOOBfill);

extern "C" void kernel_launch(void* const* d_in, const int* in_sizes, int n_in,
                              void* d_out, int out_size) {
    const void* x = nullptr; const void* w = nullptr; const void* s = nullptr;
    for (int i = 0; i < n_in; i++) {
        if      (in_sizes[i] == 33554432) x = d_in[i];
        else if (in_sizes[i] == 22544384) w = d_in[i];
        else if (in_sizes[i] == 704512)   s = d_in[i];
    }

    detect_kernel<<<1, 128>>>((const unsigned int*)x, (const unsigned int*)w,
                              (const unsigned int*)s);
    convert_x_kernel<<<16384, 256>>>(x);
    dequant_kernel<<<22016, 256>>>(w, s);

    static CUtensorMap tA, tB;
    static bool built = false;
    if (!built) {
        void* encode_raw = nullptr;
        cudaDriverEntryPointQueryResult qr;
        cudaGetDriverEntryPointByVersion("cuTensorMapEncodeTiled", &encode_raw, 12000,
                                         cudaEnableDefault, &qr);
        EncodeFn encode = (EncodeFn)encode_raw;
        void* pa = nullptr; void* pb = nullptr;
        cudaGetSymbolAddress(&pa, g_x);
        cudaGetSymbolAddress(&pb, g_deq);

        cuuint64_t dA[3] = {K_DIM, M_DIM, 1};
        cuuint64_t sA[2] = {K_DIM * 2ull, (cuuint64_t)K_DIM * M_DIM * 2ull};
        cuuint32_t bA[3] = {BK, BM, 1};
        cuuint32_t eS[3] = {1, 1, 1};
        encode(&tA, CU_TENSOR_MAP_DATA_TYPE_FLOAT16, 3, pa, dA, sA, bA, eS,
               CU_TENSOR_MAP_INTERLEAVE_NONE, CU_TENSOR_MAP_SWIZZLE_128B,
               CU_TENSOR_MAP_L2_PROMOTION_L2_128B, CU_TENSOR_MAP_FLOAT_OOB_FILL_NONE);

        cuuint64_t dB[3] = {K_DIM, N_DIM, 1};
        cuuint64_t sB[2] = {K_DIM * 2ull, (cuuint64_t)K_DIM * N_DIM * 2ull};
        cuuint32_t bB[3] = {BK, 64, 1};
        encode(&tB, CU_TENSOR_MAP_DATA_TYPE_FLOAT16, 3, pb, dB, sB, bB, eS,
               CU_TENSOR_MAP_INTERLEAVE_NONE, CU_TENSOR_MAP_SWIZZLE_128B,
               CU_TENSOR_MAP_L2_PROMOTION_L2_128B, CU_TENSOR_MAP_FLOAT_OOB_FILL_NONE);

        cudaFuncSetAttribute(gemm_tc, cudaFuncAttributeMaxDynamicSharedMemorySize,
                             SMEM_TOTAL);
        built = true;
    }

    cudaLaunchConfig_t cfg = {};
    cfg.gridDim  = {NTILES, MTILES, 1};   // (43, 64)
    cfg.blockDim = {NTHREADS, 1, 1};
    cfg.dynamicSmemBytes = SMEM_TOTAL;
    cfg.stream = 0;
    cudaLaunchAttribute attrs[1];
    attrs[0].id = cudaLaunchAttributeClusterDimension;
    attrs[0].val.clusterDim = {1, CLUSTER_M, 1};
    cfg.attrs = attrs;
    cfg.numAttrs = 1;
    cudaLaunchKernelEx(&cfg, gemm_tc, tA, tB, d_out);
}